// round 12
// baseline (speedup 1.0000x reference)
#include <cuda_runtime.h>

// Problem constants (shapes fixed by the dataset)
#define TOK   16384      // B*S tokens
#define EXP   64         // experts
#define HID   1024       // hidden H
#define DIM   1024       // expert inner dim D
#define CAP   2048       // capacity per expert

typedef unsigned long long ull;

// ---------------- scratch (device globals: no runtime allocation) ----------
static __device__ float g_logits [(size_t)TOK * EXP];   // [T][E]
static __device__ float g_logitsT[(size_t)EXP * TOK];   // [E][T]
static __device__ float g_weights[(size_t)TOK * EXP];   // softmax
static __device__ int   g_idx    [EXP * CAP];           // selected tokens
static __device__ float g_h      [(size_t)EXP * CAP * DIM]; // 512MB intermediate

// output layout (concatenated reference returns, all float32)
#define OUT_EO 0ULL
#define OUT_LI ((size_t)EXP * CAP * HID)                // 134217728
#define OUT_W  (OUT_LI + (size_t)EXP * CAP)             // +131072
#define OUT_F  (OUT_W  + (size_t)EXP * CAP)             // +131072

// ---------------- f32x2 packed-FFMA helpers (sm_100+ PTX) -----------------
__device__ __forceinline__ ull pack2(float lo, float hi) {
    ull r;
    asm("mov.b64 %0, {%1, %2};" : "=l"(r)
        : "r"(__float_as_uint(lo)), "r"(__float_as_uint(hi)));
    return r;
}
__device__ __forceinline__ void unpack2(ull v, float& lo, float& hi) {
    unsigned a, b;
    asm("mov.b64 {%0, %1}, %2;" : "=r"(a), "=r"(b) : "l"(v));
    lo = __uint_as_float(a); hi = __uint_as_float(b);
}
__device__ __forceinline__ void ffma2(ull& d, ull a, ull b) {
    asm("fma.rn.f32x2 %0, %1, %2, %0;" : "+l"(d) : "l"(a), "l"(b));
}

// ---------------- 1. router logits: BITWISE reference match -----------------
// Identified by R10 split-test: per C element the reference computes a fused
// serial FMA chain over k in [0,512), a second chain over [512,1024), then
// v = p0 + p1  (Eigen gebp with kc=512 — Grace 64KB L1d).
// Loop-carried serial chain per (t,e): no compiler reassociation possible.
// Block: 128 tokens x 64 experts; thread = (token, 32-expert half).
__global__ __launch_bounds__(256) void router_kernel(const float* __restrict__ x,
                                                     const float* __restrict__ rw) {
    __shared__ float xs[128][33];   // +1 pad: conflict-free column reads
    __shared__ float ws[64][33];
    int tid = threadIdx.x;
    int t_local = tid >> 1;          // 0..127
    int e_base  = (tid & 1) * 32;    // 0 or 32
    int t = blockIdx.x * 128 + t_local;

    float acc[32], p0[32];
    #pragma unroll
    for (int j = 0; j < 32; j++) { acc[j] = 0.f; p0[j] = 0.f; }

    for (int k0 = 0; k0 < HID; k0 += 32) {
        // stage x tile [128][32]
        #pragma unroll
        for (int s = 0; s < 4; s++) {
            int f   = tid + s * 256;        // float4 id 0..1023
            int row = f >> 3;
            int col = (f & 7) * 4;
            float4 v = *(const float4*)(x + (size_t)(blockIdx.x * 128 + row) * HID + k0 + col);
            xs[row][col + 0] = v.x; xs[row][col + 1] = v.y;
            xs[row][col + 2] = v.z; xs[row][col + 3] = v.w;
        }
        // stage rw tile [64][32]
        #pragma unroll
        for (int s = 0; s < 2; s++) {
            int f   = tid + s * 256;        // float4 id 0..511
            int row = f >> 3;
            int col = (f & 7) * 4;
            float4 v = *(const float4*)(rw + (size_t)row * HID + k0 + col);
            ws[row][col + 0] = v.x; ws[row][col + 1] = v.y;
            ws[row][col + 2] = v.z; ws[row][col + 3] = v.w;
        }
        __syncthreads();
        #pragma unroll 8
        for (int k = 0; k < 32; k++) {      // strictly ascending k per acc
            float xv = xs[t_local][k];
            #pragma unroll
            for (int j = 0; j < 32; j++)
                acc[j] = fmaf(xv, ws[e_base + j][k], acc[j]);
        }
        __syncthreads();
        if ((k0 + 32) == 512) {             // panel boundary: spill p0
            #pragma unroll
            for (int j = 0; j < 32; j++) { p0[j] = acc[j]; acc[j] = 0.f; }
        }
    }
    #pragma unroll
    for (int j = 0; j < 32; j++) {
        int e = e_base + j;
        float v = p0[j] + acc[j];           // v = p0 + p1
        g_logits [(size_t)t * EXP + e] = v;
        g_logitsT[(size_t)e * TOK + t] = v;
    }
}

// ---------------- 2. softmax over experts (per token) -----------------------
__global__ void softmax_kernel() {
    int t    = blockIdx.x * 8 + (threadIdx.x >> 5);
    int lane = threadIdx.x & 31;
    float a = g_logits[(size_t)t * EXP + lane];
    float b = g_logits[(size_t)t * EXP + lane + 32];
    float m = fmaxf(a, b);
    #pragma unroll
    for (int o = 16; o > 0; o >>= 1) m = fmaxf(m, __shfl_xor_sync(0xffffffffu, m, o));
    float ea = expf(a - m), eb = expf(b - m);
    float s = ea + eb;
    #pragma unroll
    for (int o = 16; o > 0; o >>= 1) s += __shfl_xor_sync(0xffffffffu, s, o);
    g_weights[(size_t)t * EXP + lane]      = ea / s;
    g_weights[(size_t)t * EXP + lane + 32] = eb / s;
}

// ---------------- 3. fanout zero-init (d_out is poisoned) -------------------
__global__ void zero_fanout(float* out) {
    int i = blockIdx.x * blockDim.x + threadIdx.x;
    if (i < TOK) out[OUT_F + i] = 0.f;
}

// ---------------- 4. per-expert exact top-CAP via bitonic sort --------------
// key = (~orderable(value)) << 32 | index  -> ascending sort gives
// descending value, ascending index on ties == jax.lax.top_k order.
__global__ __launch_bounds__(1024) void topk_kernel(float* __restrict__ out) {
    int e = blockIdx.x;
    extern __shared__ ull keys[];                       // 16384 * 8B = 128KB
    const int N = TOK;
    for (int i = threadIdx.x; i < N; i += blockDim.x) {
        unsigned fu  = __float_as_uint(g_logitsT[(size_t)e * N + i]);
        unsigned asc = (fu & 0x80000000u) ? ~fu : (fu | 0x80000000u);
        keys[i] = ((ull)(~asc) << 32) | (unsigned)i;
    }
    __syncthreads();
    for (int k = 2; k <= N; k <<= 1) {
        for (int j = k >> 1; j > 0; j >>= 1) {
            for (int i = threadIdx.x; i < N; i += blockDim.x) {
                int ixj = i ^ j;
                if (ixj > i) {
                    ull a = keys[i], b = keys[ixj];
                    bool up = ((i & k) == 0);
                    if ((a > b) == up) { keys[i] = b; keys[ixj] = a; }
                }
            }
            __syncthreads();
        }
    }
    for (int i = threadIdx.x; i < CAP; i += blockDim.x) {
        unsigned tok = (unsigned)(keys[i] & 0xffffffffu);
        g_idx[e * CAP + i] = (int)tok;
        out[OUT_LI + (size_t)e * CAP + i] = (float)tok;
        out[OUT_W  + (size_t)e * CAP + i] = g_weights[(size_t)tok * EXP + e];
        atomicAdd(&out[OUT_F + tok], 1.0f);
    }
}

// ---------------- 5/6. expert MLP GEMMs (NT, exact fp32, f32x2 FFMA) --------
// GATHER=1:  h = relu(x[idx] @ w1^T)^2   (A rows gathered via g_idx)
// GATHER=0:  out = h @ w2^T
// Plain fp32: elementwise rel err vs reference ~1e-6 (no ordering effects).
#define BM 128
#define BN 128
#define BK 16
#define PAD 4   // stride 132 floats: keeps 16B alignment, spreads banks

template <int GATHER>
__global__ __launch_bounds__(256, 2)
void mlp_gemm(const float* __restrict__ A_src,
              const float* __restrict__ Bmat,
              float* __restrict__ Out) {
    int e  = blockIdx.z;
    int mt = blockIdx.y;   // 0..15
    int nt = blockIdx.x;   // 0..7
    __shared__ __align__(16) float As[BK][BM + PAD];
    __shared__ __align__(16) float Bs[BK][BN + PAD];
    __shared__ int toks[BM];
    int tid = threadIdx.x;
    if (GATHER && tid < BM) toks[tid] = g_idx[e * CAP + mt * BM + tid];
    __syncthreads();

    const float* Bbase = Bmat + ((size_t)e * 1024 + (size_t)nt * BN) * 1024;
    int tx = tid & 15, ty = tid >> 4;

    ull acc[8][4];
    #pragma unroll
    for (int i = 0; i < 8; i++)
        #pragma unroll
        for (int j = 0; j < 4; j++) acc[i][j] = 0ULL;

    for (int k0 = 0; k0 < 1024; k0 += BK) {
        // stage A tile (transposed into [k][m])
        #pragma unroll
        for (int s = 0; s < 2; s++) {
            int f4  = tid + s * 256;        // 0..511
            int row = f4 >> 2;
            int kc  = (f4 & 3) * 4;
            const float* ap;
            if (GATHER)
                ap = A_src + (size_t)toks[row] * 1024 + k0 + kc;
            else
                ap = g_h + ((size_t)e * CAP + (size_t)mt * BM + row) * 1024 + k0 + kc;
            float4 v = *(const float4*)ap;
            As[kc + 0][row] = v.x; As[kc + 1][row] = v.y;
            As[kc + 2][row] = v.z; As[kc + 3][row] = v.w;
        }
        // stage B tile
        #pragma unroll
        for (int s = 0; s < 2; s++) {
            int f4  = tid + s * 256;
            int row = f4 >> 2;
            int kc  = (f4 & 3) * 4;
            float4 v = *(const float4*)(Bbase + (size_t)row * 1024 + k0 + kc);
            Bs[kc + 0][row] = v.x; Bs[kc + 1][row] = v.y;
            Bs[kc + 2][row] = v.z; Bs[kc + 3][row] = v.w;
        }
        __syncthreads();

        #pragma unroll
        for (int k = 0; k < BK; k++) {
            float4 a0 = *(const float4*)&As[k][ty * 8];
            float4 a1 = *(const float4*)&As[k][ty * 8 + 4];
            const ull* bp = (const ull*)&Bs[k][tx * 8];
            ull b0 = bp[0], b1 = bp[1], b2 = bp[2], b3 = bp[3];
            ull A2[8];
            A2[0] = pack2(a0.x, a0.x); A2[1] = pack2(a0.y, a0.y);
            A2[2] = pack2(a0.z, a0.z); A2[3] = pack2(a0.w, a0.w);
            A2[4] = pack2(a1.x, a1.x); A2[5] = pack2(a1.y, a1.y);
            A2[6] = pack2(a1.z, a1.z); A2[7] = pack2(a1.w, a1.w);
            #pragma unroll
            for (int i = 0; i < 8; i++) {
                ffma2(acc[i][0], A2[i], b0);
                ffma2(acc[i][1], A2[i], b1);
                ffma2(acc[i][2], A2[i], b2);
                ffma2(acc[i][3], A2[i], b3);
            }
        }
        __syncthreads();
    }

    // epilogue
    size_t rowbase = (size_t)e * CAP + (size_t)mt * BM;
    #pragma unroll
    for (int i = 0; i < 8; i++) {
        float* orow;
        if (GATHER)
            orow = g_h + (rowbase + ty * 8 + i) * 1024 + nt * BN + tx * 8;
        else
            orow = Out + (rowbase + ty * 8 + i) * 1024 + nt * BN + tx * 8;
        #pragma unroll
        for (int j = 0; j < 4; j++) {
            float lo, hi;
            unpack2(acc[i][j], lo, hi);
            if (GATHER) {                       // relu^2
                lo = (lo > 0.f) ? lo * lo : 0.f;
                hi = (hi > 0.f) ? hi * hi : 0.f;
            }
            orow[2 * j]     = lo;
            orow[2 * j + 1] = hi;
        }
    }
}

// ---------------- launch ----------------------------------------------------
extern "C" void kernel_launch(void* const* d_in, const int* in_sizes, int n_in,
                              void* d_out, int out_size) {
    const float* x  = (const float*)d_in[0];
    const float* rw = (const float*)d_in[1];
    const float* w1 = (const float*)d_in[2];
    const float* w2 = (const float*)d_in[3];
    float* out = (float*)d_out;

    cudaFuncSetAttribute(topk_kernel,
                         cudaFuncAttributeMaxDynamicSharedMemorySize, 131072);

    router_kernel<<<TOK / 128, 256>>>(x, rw);
    softmax_kernel<<<TOK / 8, 256>>>();
    zero_fanout<<<TOK / 256, 256>>>(out);
    topk_kernel<<<EXP, 1024, 131072>>>(out);
    mlp_gemm<1><<<dim3(8, 16, 64), 256>>>(x, w1, nullptr);
    mlp_gemm<0><<<dim3(8, 16, 64), 256>>>(nullptr, w2, out);
}

// round 14
// speedup vs baseline: 2.4824x; 2.4824x over previous
#include <cuda_runtime.h>
#include <cstdint>

// Problem constants
#define TOK   16384
#define EXP   64
#define HID   1024
#define DIM   1024
#define CAP   2048

typedef unsigned long long ull;

// ---------------- scratch (device globals) ----------------------------------
static __device__ float g_logits [(size_t)TOK * EXP];
static __device__ float g_logitsT[(size_t)EXP * TOK];
static __device__ float g_weights[(size_t)TOK * EXP];
static __device__ int   g_idx    [EXP * CAP];
// 3xTF32 split operand buffers
static __device__ float g_xhi [(size_t)TOK * HID];
static __device__ float g_xlo [(size_t)TOK * HID];
static __device__ float g_w1hi[(size_t)EXP * DIM * HID];
static __device__ float g_w1lo[(size_t)EXP * DIM * HID];
static __device__ float g_w2hi[(size_t)EXP * HID * DIM];
static __device__ float g_w2lo[(size_t)EXP * HID * DIM];
static __device__ float g_hhi [(size_t)EXP * CAP * DIM];
static __device__ float g_hlo [(size_t)EXP * CAP * DIM];

// output layout
#define OUT_LI ((size_t)EXP * CAP * HID)
#define OUT_W  (OUT_LI + (size_t)EXP * CAP)
#define OUT_F  (OUT_W  + (size_t)EXP * CAP)

// ---------------- helpers ----------------------------------------------------
__device__ __forceinline__ float to_tf32(float a) {
    float r;
    asm("cvt.rna.tf32.f32 %0, %1;" : "=f"(r) : "f"(a));
    return r;
}
__device__ __forceinline__ uint32_t smem_u32(const void* p) {
    uint32_t a;
    asm("{ .reg .u64 t; cvta.to.shared.u64 t, %1; cvt.u32.u64 %0, t; }" : "=r"(a) : "l"(p));
    return a;
}
__device__ __forceinline__ void cp16(uint32_t dst, const float* src) {
    asm volatile("cp.async.cg.shared.global [%0], [%1], 16;" :: "r"(dst), "l"(src));
}
#define CP_COMMIT() asm volatile("cp.async.commit_group;" ::: "memory")
template <int N> __device__ __forceinline__ void cp_wait() {
    asm volatile("cp.async.wait_group %0;" :: "n"(N) : "memory");
}

// m16n8k8 tf32 tensor-core MMA (baseline PTX, works on compute_103)
__device__ __forceinline__ void mma8(float* c, const uint32_t* a, uint32_t b0, uint32_t b1) {
    asm volatile(
        "mma.sync.aligned.m16n8k8.row.col.f32.tf32.tf32.f32 "
        "{%0,%1,%2,%3}, {%4,%5,%6,%7}, {%8,%9}, {%0,%1,%2,%3};"
        : "+f"(c[0]), "+f"(c[1]), "+f"(c[2]), "+f"(c[3])
        : "r"(a[0]), "r"(a[1]), "r"(a[2]), "r"(a[3]), "r"(b0), "r"(b1));
}

// ---------------- 0. hi/lo tf32 split pre-pass -------------------------------
__global__ void split_kernel(const float4* __restrict__ src,
                             float4* __restrict__ hi, float4* __restrict__ lo, int n4) {
    for (int i = blockIdx.x * blockDim.x + threadIdx.x; i < n4; i += gridDim.x * blockDim.x) {
        float4 v = src[i];
        float4 h, l;
        h.x = to_tf32(v.x); l.x = to_tf32(v.x - h.x);
        h.y = to_tf32(v.y); l.y = to_tf32(v.y - h.y);
        h.z = to_tf32(v.z); l.z = to_tf32(v.z - h.z);
        h.w = to_tf32(v.w); l.w = to_tf32(v.w - h.w);
        hi[i] = h; lo[i] = l;
    }
}

// ---------------- 1. router logits: BITWISE reference match (kc=512) --------
__global__ __launch_bounds__(256) void router_kernel(const float* __restrict__ x,
                                                     const float* __restrict__ rw) {
    __shared__ float xs[128][33];
    __shared__ float ws[64][33];
    int tid = threadIdx.x;
    int t_local = tid >> 1;
    int e_base  = (tid & 1) * 32;
    int t = blockIdx.x * 128 + t_local;

    float acc[32], p0[32];
    #pragma unroll
    for (int j = 0; j < 32; j++) { acc[j] = 0.f; p0[j] = 0.f; }

    for (int k0 = 0; k0 < HID; k0 += 32) {
        #pragma unroll
        for (int s = 0; s < 4; s++) {
            int f = tid + s * 256;
            int row = f >> 3, col = (f & 7) * 4;
            float4 v = *(const float4*)(x + (size_t)(blockIdx.x * 128 + row) * HID + k0 + col);
            xs[row][col + 0] = v.x; xs[row][col + 1] = v.y;
            xs[row][col + 2] = v.z; xs[row][col + 3] = v.w;
        }
        #pragma unroll
        for (int s = 0; s < 2; s++) {
            int f = tid + s * 256;
            int row = f >> 3, col = (f & 7) * 4;
            float4 v = *(const float4*)(rw + (size_t)row * HID + k0 + col);
            ws[row][col + 0] = v.x; ws[row][col + 1] = v.y;
            ws[row][col + 2] = v.z; ws[row][col + 3] = v.w;
        }
        __syncthreads();
        #pragma unroll 8
        for (int k = 0; k < 32; k++) {
            float xv = xs[t_local][k];
            #pragma unroll
            for (int j = 0; j < 32; j++)
                acc[j] = fmaf(xv, ws[e_base + j][k], acc[j]);
        }
        __syncthreads();
        if ((k0 + 32) == 512) {
            #pragma unroll
            for (int j = 0; j < 32; j++) { p0[j] = acc[j]; acc[j] = 0.f; }
        }
    }
    #pragma unroll
    for (int j = 0; j < 32; j++) {
        int e = e_base + j;
        float v = p0[j] + acc[j];
        g_logits [(size_t)t * EXP + e] = v;
        g_logitsT[(size_t)e * TOK + t] = v;
    }
}

// ---------------- 2. softmax -------------------------------------------------
__global__ void softmax_kernel() {
    int t    = blockIdx.x * 8 + (threadIdx.x >> 5);
    int lane = threadIdx.x & 31;
    float a = g_logits[(size_t)t * EXP + lane];
    float b = g_logits[(size_t)t * EXP + lane + 32];
    float m = fmaxf(a, b);
    #pragma unroll
    for (int o = 16; o > 0; o >>= 1) m = fmaxf(m, __shfl_xor_sync(0xffffffffu, m, o));
    float ea = expf(a - m), eb = expf(b - m);
    float s = ea + eb;
    #pragma unroll
    for (int o = 16; o > 0; o >>= 1) s += __shfl_xor_sync(0xffffffffu, s, o);
    g_weights[(size_t)t * EXP + lane]      = ea / s;
    g_weights[(size_t)t * EXP + lane + 32] = eb / s;
}

// ---------------- 3. fanout zero-init ---------------------------------------
__global__ void zero_fanout(float* out) {
    int i = blockIdx.x * blockDim.x + threadIdx.x;
    if (i < TOK) out[OUT_F + i] = 0.f;
}

// ---------------- 4. exact top-CAP bitonic sort ------------------------------
__global__ __launch_bounds__(1024) void topk_kernel(float* __restrict__ out) {
    int e = blockIdx.x;
    extern __shared__ ull keys[];
    const int N = TOK;
    for (int i = threadIdx.x; i < N; i += blockDim.x) {
        unsigned fu  = __float_as_uint(g_logitsT[(size_t)e * N + i]);
        unsigned asc = (fu & 0x80000000u) ? ~fu : (fu | 0x80000000u);
        keys[i] = ((ull)(~asc) << 32) | (unsigned)i;
    }
    __syncthreads();
    for (int k = 2; k <= N; k <<= 1) {
        for (int j = k >> 1; j > 0; j >>= 1) {
            for (int i = threadIdx.x; i < N; i += blockDim.x) {
                int ixj = i ^ j;
                if (ixj > i) {
                    ull a = keys[i], b = keys[ixj];
                    bool up = ((i & k) == 0);
                    if ((a > b) == up) { keys[i] = b; keys[ixj] = a; }
                }
            }
            __syncthreads();
        }
    }
    for (int i = threadIdx.x; i < CAP; i += blockDim.x) {
        unsigned tok = (unsigned)(keys[i] & 0xffffffffu);
        g_idx[e * CAP + i] = (int)tok;
        out[OUT_LI + (size_t)e * CAP + i] = (float)tok;
        out[OUT_W  + (size_t)e * CAP + i] = g_weights[(size_t)tok * EXP + e];
        atomicAdd(&out[OUT_F + tok], 1.0f);
    }
}

// ---------------- 5/6. 3xTF32 mma.sync expert GEMMs --------------------------
// CTA tile 256(M) x 128(N), 8 warps (4x2), warp tile 64x64 (4 m16 x 8 n8).
// k-chunk 16, 2-stage cp.async pipeline. D += AhiBhi + AhiBlo + AloBhi.
#define BKC    16
#define NCHUNK (HID / BKC)          // 64
#define KPAD   20                   // stride 20 floats: conflict-free frag LDS
#define SA_HI  0
#define SA_LO  (256 * KPAD)         // 5120
#define SB_HI  (2 * 256 * KPAD)     // 10240
#define SB_LO  (2 * 256 * KPAD + 128 * KPAD)
#define STAGE_F (2 * 256 * KPAD + 2 * 128 * KPAD)   // 15360 floats
#define GEMM_SMEM (2 * STAGE_F * 4)                  // 122880 bytes

template <int GATHER>
__device__ __forceinline__ void stage(
    float* buf, int c, int e, int mt, int nt,
    const float* __restrict__ Ahi, const float* __restrict__ Alo,
    const float* __restrict__ Bhi, const float* __restrict__ Blo,
    const int* toks) {
    int tid = threadIdx.x;
    int k0 = c * BKC;
    uint32_t base = smem_u32(buf);
    // A: 256 rows x 16 floats  (1024 float4 slots per hi/lo)
    #pragma unroll
    for (int s = 0; s < 4; s++) {
        int u = tid + s * 256;
        int row = u >> 2, c4 = (u & 3) * 4;
        size_t srow = GATHER ? (size_t)toks[row]
                             : ((size_t)e * CAP + (size_t)mt * 256 + row);
        size_t off = srow * (size_t)HID + k0 + c4;
        uint32_t d = (uint32_t)(row * KPAD + c4) * 4;
        cp16(base + SA_HI * 4 + d, Ahi + off);
        cp16(base + SA_LO * 4 + d, Alo + off);
    }
    // B: 128 rows x 16 floats  (512 float4 slots per hi/lo)
    #pragma unroll
    for (int s = 0; s < 2; s++) {
        int u = tid + s * 256;
        int row = u >> 2, c4 = (u & 3) * 4;
        size_t off = ((size_t)e * 1024 + (size_t)nt * 128 + row) * (size_t)HID + k0 + c4;
        uint32_t d = (uint32_t)(row * KPAD + c4) * 4;
        cp16(base + SB_HI * 4 + d, Bhi + off);
        cp16(base + SB_LO * 4 + d, Blo + off);
    }
}

template <int GATHER>
__global__ __launch_bounds__(256, 1) void moe_gemm(
    const float* __restrict__ Ahi, const float* __restrict__ Alo,
    const float* __restrict__ Bhi, const float* __restrict__ Blo,
    float* __restrict__ OutHi, float* __restrict__ OutLo) {
    extern __shared__ float smf[];
    int e = blockIdx.z, mt = blockIdx.y, nt = blockIdx.x;
    int tid = threadIdx.x, wid = tid >> 5, lid = tid & 31;
    int wm = wid >> 1, wn = wid & 1;           // 4 x 2 warp grid
    int g = lid >> 2, t = lid & 3;

    __shared__ int toks[256];
    if (GATHER) {
        if (tid < 256) toks[tid] = g_idx[e * CAP + mt * 256 + tid];
        __syncthreads();
    }

    float cfr[4][8][4];
    #pragma unroll
    for (int i = 0; i < 4; i++)
        #pragma unroll
        for (int j = 0; j < 8; j++)
            #pragma unroll
            for (int r = 0; r < 4; r++) cfr[i][j][r] = 0.f;

    stage<GATHER>(smf, 0, e, mt, nt, Ahi, Alo, Bhi, Blo, toks);
    CP_COMMIT();
    stage<GATHER>(smf + STAGE_F, 1, e, mt, nt, Ahi, Alo, Bhi, Blo, toks);
    CP_COMMIT();

    for (int c = 0; c < NCHUNK; c++) {
        float* buf = smf + (c & 1) * STAGE_F;
        if (c == NCHUNK - 1) cp_wait<0>(); else cp_wait<1>();
        __syncthreads();

        const float* Ah = buf + SA_HI;
        const float* Al = buf + SA_LO;
        const float* Bh = buf + SB_HI;
        const float* Bl = buf + SB_LO;

        #pragma unroll
        for (int kk = 0; kk < BKC; kk += 8) {
            uint32_t ah[4][4], al[4][4];
            #pragma unroll
            for (int i = 0; i < 4; i++) {
                int r0 = wm * 64 + i * 16 + g;
                int cA = kk + t;
                ah[i][0] = __float_as_uint(Ah[r0 * KPAD + cA]);
                ah[i][1] = __float_as_uint(Ah[(r0 + 8) * KPAD + cA]);
                ah[i][2] = __float_as_uint(Ah[r0 * KPAD + cA + 4]);
                ah[i][3] = __float_as_uint(Ah[(r0 + 8) * KPAD + cA + 4]);
                al[i][0] = __float_as_uint(Al[r0 * KPAD + cA]);
                al[i][1] = __float_as_uint(Al[(r0 + 8) * KPAD + cA]);
                al[i][2] = __float_as_uint(Al[r0 * KPAD + cA + 4]);
                al[i][3] = __float_as_uint(Al[(r0 + 8) * KPAD + cA + 4]);
            }
            #pragma unroll
            for (int j = 0; j < 8; j++) {
                int nr = wn * 64 + j * 8 + g;
                uint32_t bh0 = __float_as_uint(Bh[nr * KPAD + kk + t]);
                uint32_t bh1 = __float_as_uint(Bh[nr * KPAD + kk + t + 4]);
                uint32_t bl0 = __float_as_uint(Bl[nr * KPAD + kk + t]);
                uint32_t bl1 = __float_as_uint(Bl[nr * KPAD + kk + t + 4]);
                #pragma unroll
                for (int i = 0; i < 4; i++) {
                    mma8(cfr[i][j], ah[i], bh0, bh1);
                    mma8(cfr[i][j], ah[i], bl0, bl1);
                    mma8(cfr[i][j], al[i], bh0, bh1);
                }
            }
        }
        __syncthreads();
        if (c + 2 < NCHUNK) {
            stage<GATHER>(buf, c + 2, e, mt, nt, Ahi, Alo, Bhi, Blo, toks);
            CP_COMMIT();
        }
    }

    // epilogue
    #pragma unroll
    for (int i = 0; i < 4; i++) {
        size_t row0 = (size_t)e * CAP + (size_t)mt * 256 + wm * 64 + i * 16 + g;
        #pragma unroll
        for (int j = 0; j < 8; j++) {
            size_t col = (size_t)nt * 128 + wn * 64 + j * 8 + 2 * t;
            #pragma unroll
            for (int h = 0; h < 2; h++) {          // h=0: rows g, h=1: rows g+8
                size_t row = row0 + h * 8;
                float v0 = cfr[i][j][2 * h + 0];
                float v1 = cfr[i][j][2 * h + 1];
                if (GATHER) {
                    v0 = (v0 > 0.f) ? v0 * v0 : 0.f;
                    v1 = (v1 > 0.f) ? v1 * v1 : 0.f;
                    float h0 = to_tf32(v0), h1 = to_tf32(v1);
                    *(float2*)(OutHi + row * (size_t)DIM + col) = make_float2(h0, h1);
                    *(float2*)(OutLo + row * (size_t)DIM + col) =
                        make_float2(to_tf32(v0 - h0), to_tf32(v1 - h1));
                } else {
                    *(float2*)(OutHi + row * (size_t)HID + col) = make_float2(v0, v1);
                }
            }
        }
    }
}

// ---------------- launch -----------------------------------------------------
extern "C" void kernel_launch(void* const* d_in, const int* in_sizes, int n_in,
                              void* d_out, int out_size) {
    const float* x  = (const float*)d_in[0];
    const float* rw = (const float*)d_in[1];
    const float* w1 = (const float*)d_in[2];
    const float* w2 = (const float*)d_in[3];
    float* out = (float*)d_out;

    cudaFuncSetAttribute(topk_kernel,
                         cudaFuncAttributeMaxDynamicSharedMemorySize, 131072);
    cudaFuncSetAttribute(moe_gemm<1>,
                         cudaFuncAttributeMaxDynamicSharedMemorySize, GEMM_SMEM);
    cudaFuncSetAttribute(moe_gemm<0>,
                         cudaFuncAttributeMaxDynamicSharedMemorySize, GEMM_SMEM);

    void *xhi, *xlo, *w1hi, *w1lo, *w2hi, *w2lo, *hhi, *hlo;
    cudaGetSymbolAddress(&xhi,  g_xhi);  cudaGetSymbolAddress(&xlo,  g_xlo);
    cudaGetSymbolAddress(&w1hi, g_w1hi); cudaGetSymbolAddress(&w1lo, g_w1lo);
    cudaGetSymbolAddress(&w2hi, g_w2hi); cudaGetSymbolAddress(&w2lo, g_w2lo);
    cudaGetSymbolAddress(&hhi,  g_hhi);  cudaGetSymbolAddress(&hlo,  g_hlo);

    split_kernel<<<2048, 256>>>((const float4*)x,  (float4*)xhi,  (float4*)xlo,  TOK * HID / 4);
    split_kernel<<<4096, 256>>>((const float4*)w1, (float4*)w1hi, (float4*)w1lo, EXP * DIM * HID / 4);
    split_kernel<<<4096, 256>>>((const float4*)w2, (float4*)w2hi, (float4*)w2lo, EXP * HID * DIM / 4);

    router_kernel<<<TOK / 128, 256>>>(x, rw);
    softmax_kernel<<<TOK / 8, 256>>>();
    zero_fanout<<<TOK / 256, 256>>>(out);
    topk_kernel<<<EXP, 1024, 131072>>>(out);

    // GEMM1: h = split(relu(x[idx] @ w1^T)^2)   grid (N tiles, M tiles, E)
    moe_gemm<1><<<dim3(DIM / 128, CAP / 256, EXP), 256, GEMM_SMEM>>>(
        (const float*)xhi, (const float*)xlo, (const float*)w1hi, (const float*)w1lo,
        (float*)hhi, (float*)hlo);
    // GEMM2: out = h @ w2^T
    moe_gemm<0><<<dim3(HID / 128, CAP / 256, EXP), 256, GEMM_SMEM>>>(
        (const float*)hhi, (const float*)hlo, (const float*)w2hi, (const float*)w2lo,
        out, nullptr);
}

// round 15
// speedup vs baseline: 2.9163x; 1.1748x over previous
#include <cuda_runtime.h>
#include <cstdint>

// Problem constants
#define TOK   16384
#define EXP   64
#define HID   1024
#define DIM   1024
#define CAP   2048

typedef unsigned long long ull;

// ---------------- scratch (device globals) ----------------------------------
static __device__ float g_logits [(size_t)TOK * EXP];
static __device__ float g_logitsT[(size_t)EXP * TOK];
static __device__ float g_weights[(size_t)TOK * EXP];
static __device__ int   g_idx    [EXP * CAP];
static __device__ float g_h      [(size_t)EXP * CAP * DIM];   // fp32 intermediate

// output layout
#define OUT_LI ((size_t)EXP * CAP * HID)
#define OUT_W  (OUT_LI + (size_t)EXP * CAP)
#define OUT_F  (OUT_W  + (size_t)EXP * CAP)

// ---------------- helpers ----------------------------------------------------
__device__ __forceinline__ uint32_t smem_u32(const void* p) {
    uint32_t a;
    asm("{ .reg .u64 t; cvta.to.shared.u64 t, %1; cvt.u32.u64 %0, t; }" : "=r"(a) : "l"(p));
    return a;
}
__device__ __forceinline__ void cp16(uint32_t dst, const float* src) {
    asm volatile("cp.async.cg.shared.global [%0], [%1], 16;" :: "r"(dst), "l"(src));
}
#define CP_COMMIT() asm volatile("cp.async.commit_group;" ::: "memory")
template <int N> __device__ __forceinline__ void cp_wait() {
    asm volatile("cp.async.wait_group %0;" :: "n"(N) : "memory");
}

// tf32 bitmask split: hi keeps top-10 mantissa bits (exact in tf32), lo = v-hi
__device__ __forceinline__ void tf32_split(float v, uint32_t& hi, uint32_t& lo) {
    uint32_t h = __float_as_uint(v) & 0xFFFFE000u;
    hi = h;
    lo = __float_as_uint(v - __uint_as_float(h));
}

// m16n8k8 tf32 tensor-core MMA (baseline PTX, works on compute_103)
__device__ __forceinline__ void mma8(float* c, const uint32_t* a, uint32_t b0, uint32_t b1) {
    asm volatile(
        "mma.sync.aligned.m16n8k8.row.col.f32.tf32.tf32.f32 "
        "{%0,%1,%2,%3}, {%4,%5,%6,%7}, {%8,%9}, {%0,%1,%2,%3};"
        : "+f"(c[0]), "+f"(c[1]), "+f"(c[2]), "+f"(c[3])
        : "r"(a[0]), "r"(a[1]), "r"(a[2]), "r"(a[3]), "r"(b0), "r"(b1));
}

// ---------------- 1. router logits: BITWISE reference match (kc=512) --------
__global__ __launch_bounds__(256) void router_kernel(const float* __restrict__ x,
                                                     const float* __restrict__ rw) {
    __shared__ float xs[128][33];
    __shared__ float ws[64][33];
    int tid = threadIdx.x;
    int t_local = tid >> 1;
    int e_base  = (tid & 1) * 32;
    int t = blockIdx.x * 128 + t_local;

    float acc[32], p0[32];
    #pragma unroll
    for (int j = 0; j < 32; j++) { acc[j] = 0.f; p0[j] = 0.f; }

    for (int k0 = 0; k0 < HID; k0 += 32) {
        #pragma unroll
        for (int s = 0; s < 4; s++) {
            int f = tid + s * 256;
            int row = f >> 3, col = (f & 7) * 4;
            float4 v = *(const float4*)(x + (size_t)(blockIdx.x * 128 + row) * HID + k0 + col);
            xs[row][col + 0] = v.x; xs[row][col + 1] = v.y;
            xs[row][col + 2] = v.z; xs[row][col + 3] = v.w;
        }
        #pragma unroll
        for (int s = 0; s < 2; s++) {
            int f = tid + s * 256;
            int row = f >> 3, col = (f & 7) * 4;
            float4 v = *(const float4*)(rw + (size_t)row * HID + k0 + col);
            ws[row][col + 0] = v.x; ws[row][col + 1] = v.y;
            ws[row][col + 2] = v.z; ws[row][col + 3] = v.w;
        }
        __syncthreads();
        #pragma unroll 8
        for (int k = 0; k < 32; k++) {
            float xv = xs[t_local][k];
            #pragma unroll
            for (int j = 0; j < 32; j++)
                acc[j] = fmaf(xv, ws[e_base + j][k], acc[j]);
        }
        __syncthreads();
        if ((k0 + 32) == 512) {
            #pragma unroll
            for (int j = 0; j < 32; j++) { p0[j] = acc[j]; acc[j] = 0.f; }
        }
    }
    #pragma unroll
    for (int j = 0; j < 32; j++) {
        int e = e_base + j;
        float v = p0[j] + acc[j];
        g_logits [(size_t)t * EXP + e] = v;
        g_logitsT[(size_t)e * TOK + t] = v;
    }
}

// ---------------- 2. softmax -------------------------------------------------
__global__ void softmax_kernel() {
    int t    = blockIdx.x * 8 + (threadIdx.x >> 5);
    int lane = threadIdx.x & 31;
    float a = g_logits[(size_t)t * EXP + lane];
    float b = g_logits[(size_t)t * EXP + lane + 32];
    float m = fmaxf(a, b);
    #pragma unroll
    for (int o = 16; o > 0; o >>= 1) m = fmaxf(m, __shfl_xor_sync(0xffffffffu, m, o));
    float ea = expf(a - m), eb = expf(b - m);
    float s = ea + eb;
    #pragma unroll
    for (int o = 16; o > 0; o >>= 1) s += __shfl_xor_sync(0xffffffffu, s, o);
    g_weights[(size_t)t * EXP + lane]      = ea / s;
    g_weights[(size_t)t * EXP + lane + 32] = eb / s;
}

// ---------------- 3. fanout zero-init ---------------------------------------
__global__ void zero_fanout(float* out) {
    int i = blockIdx.x * blockDim.x + threadIdx.x;
    if (i < TOK) out[OUT_F + i] = 0.f;
}

// ---------------- 4. exact top-CAP bitonic sort ------------------------------
__global__ __launch_bounds__(1024) void topk_kernel(float* __restrict__ out) {
    int e = blockIdx.x;
    extern __shared__ ull keys[];
    const int N = TOK;
    for (int i = threadIdx.x; i < N; i += blockDim.x) {
        unsigned fu  = __float_as_uint(g_logitsT[(size_t)e * N + i]);
        unsigned asc = (fu & 0x80000000u) ? ~fu : (fu | 0x80000000u);
        keys[i] = ((ull)(~asc) << 32) | (unsigned)i;
    }
    __syncthreads();
    for (int k = 2; k <= N; k <<= 1) {
        for (int j = k >> 1; j > 0; j >>= 1) {
            for (int i = threadIdx.x; i < N; i += blockDim.x) {
                int ixj = i ^ j;
                if (ixj > i) {
                    ull a = keys[i], b = keys[ixj];
                    bool up = ((i & k) == 0);
                    if ((a > b) == up) { keys[i] = b; keys[ixj] = a; }
                }
            }
            __syncthreads();
        }
    }
    for (int i = threadIdx.x; i < CAP; i += blockDim.x) {
        unsigned tok = (unsigned)(keys[i] & 0xffffffffu);
        g_idx[e * CAP + i] = (int)tok;
        out[OUT_LI + (size_t)e * CAP + i] = (float)tok;
        out[OUT_W  + (size_t)e * CAP + i] = g_weights[(size_t)tok * EXP + e];
        atomicAdd(&out[OUT_F + tok], 1.0f);
    }
}

// ---------------- 5/6. 3xTF32 mma.sync expert GEMMs --------------------------
// CTA tile 256(M) x 128(N), 8 warps (4x2), warp tile 64x64.
// fp32 staged ONCE; tf32 hi/lo derived in registers (mask split).
// k-chunk 16, 2-stage cp.async pipeline. D += AhiBhi + AhiBlo + AloBhi.
#define BKC    16
#define NCHUNK (HID / BKC)          // 64
#define KPAD   20                   // conflict-free fragment LDS
#define SA     0
#define SB     (256 * KPAD)
#define STAGE_F ((256 + 128) * KPAD)                // 7680 floats = 30720 B
#define GEMM_SMEM (2 * STAGE_F * 4)                 // 61440 B

template <int GATHER>
__device__ __forceinline__ void stage(
    float* buf, int c, int e, int mt, int nt,
    const float* __restrict__ A, const float* __restrict__ B,
    const int* toks) {
    int tid = threadIdx.x;
    int k0 = c * BKC;
    uint32_t base = smem_u32(buf);
    // A: 256 rows x 16 floats = 1024 float4
    #pragma unroll
    for (int s = 0; s < 4; s++) {
        int u = tid + s * 256;
        int row = u >> 2, c4 = (u & 3) * 4;
        size_t srow = GATHER ? (size_t)toks[row]
                             : ((size_t)e * CAP + (size_t)mt * 256 + row);
        cp16(base + (uint32_t)(row * KPAD + c4) * 4, A + srow * (size_t)HID + k0 + c4);
    }
    // B: 128 rows x 16 floats = 512 float4
    #pragma unroll
    for (int s = 0; s < 2; s++) {
        int u = tid + s * 256;
        int row = u >> 2, c4 = (u & 3) * 4;
        size_t off = ((size_t)e * 1024 + (size_t)nt * 128 + row) * (size_t)HID + k0 + c4;
        cp16(base + (uint32_t)(SB + row * KPAD + c4) * 4, B + off);
    }
}

template <int GATHER>
__global__ __launch_bounds__(256, 1) void moe_gemm(
    const float* __restrict__ A, const float* __restrict__ B,
    float* __restrict__ Out) {
    extern __shared__ float smf[];
    int e = blockIdx.z, mt = blockIdx.y, nt = blockIdx.x;
    int tid = threadIdx.x, wid = tid >> 5, lid = tid & 31;
    int wm = wid >> 1, wn = wid & 1;           // 4 x 2 warp grid
    int g = lid >> 2, t = lid & 3;

    __shared__ int toks[256];
    if (GATHER) {
        if (tid < 256) toks[tid] = g_idx[e * CAP + mt * 256 + tid];
        __syncthreads();
    }

    float cfr[4][8][4];
    #pragma unroll
    for (int i = 0; i < 4; i++)
        #pragma unroll
        for (int j = 0; j < 8; j++)
            #pragma unroll
            for (int r = 0; r < 4; r++) cfr[i][j][r] = 0.f;

    stage<GATHER>(smf, 0, e, mt, nt, A, B, toks);
    CP_COMMIT();
    stage<GATHER>(smf + STAGE_F, 1, e, mt, nt, A, B, toks);
    CP_COMMIT();

    for (int c = 0; c < NCHUNK; c++) {
        float* buf = smf + (c & 1) * STAGE_F;
        if (c == NCHUNK - 1) cp_wait<0>(); else cp_wait<1>();
        __syncthreads();

        const float* As = buf + SA;
        const float* Bs = buf + SB;

        #pragma unroll
        for (int kk = 0; kk < BKC; kk += 8) {
            uint32_t ah[4][4], al[4][4];
            #pragma unroll
            for (int i = 0; i < 4; i++) {
                int r0 = wm * 64 + i * 16 + g;
                int cA = kk + t;
                tf32_split(As[r0 * KPAD + cA],           ah[i][0], al[i][0]);
                tf32_split(As[(r0 + 8) * KPAD + cA],     ah[i][1], al[i][1]);
                tf32_split(As[r0 * KPAD + cA + 4],       ah[i][2], al[i][2]);
                tf32_split(As[(r0 + 8) * KPAD + cA + 4], ah[i][3], al[i][3]);
            }
            #pragma unroll
            for (int j = 0; j < 8; j++) {
                int nr = wn * 64 + j * 8 + g;
                uint32_t bh0, bl0, bh1, bl1;
                tf32_split(Bs[nr * KPAD + kk + t],     bh0, bl0);
                tf32_split(Bs[nr * KPAD + kk + t + 4], bh1, bl1);
                #pragma unroll
                for (int i = 0; i < 4; i++) {
                    mma8(cfr[i][j], ah[i], bh0, bh1);
                    mma8(cfr[i][j], ah[i], bl0, bl1);
                    mma8(cfr[i][j], al[i], bh0, bh1);
                }
            }
        }
        __syncthreads();
        if (c + 2 < NCHUNK) {
            stage<GATHER>(buf, c + 2, e, mt, nt, A, B, toks);
            CP_COMMIT();
        }
    }

    // epilogue
    #pragma unroll
    for (int i = 0; i < 4; i++) {
        size_t row0 = (size_t)e * CAP + (size_t)mt * 256 + wm * 64 + i * 16 + g;
        #pragma unroll
        for (int j = 0; j < 8; j++) {
            size_t col = (size_t)nt * 128 + wn * 64 + j * 8 + 2 * t;
            #pragma unroll
            for (int h = 0; h < 2; h++) {
                size_t row = row0 + h * 8;
                float v0 = cfr[i][j][2 * h + 0];
                float v1 = cfr[i][j][2 * h + 1];
                if (GATHER) {                         // relu^2
                    v0 = (v0 > 0.f) ? v0 * v0 : 0.f;
                    v1 = (v1 > 0.f) ? v1 * v1 : 0.f;
                }
                *(float2*)(Out + row * (size_t)HID + col) = make_float2(v0, v1);
            }
        }
    }
}

// ---------------- launch -----------------------------------------------------
extern "C" void kernel_launch(void* const* d_in, const int* in_sizes, int n_in,
                              void* d_out, int out_size) {
    const float* x  = (const float*)d_in[0];
    const float* rw = (const float*)d_in[1];
    const float* w1 = (const float*)d_in[2];
    const float* w2 = (const float*)d_in[3];
    float* out = (float*)d_out;

    cudaFuncSetAttribute(topk_kernel,
                         cudaFuncAttributeMaxDynamicSharedMemorySize, 131072);
    cudaFuncSetAttribute(moe_gemm<1>,
                         cudaFuncAttributeMaxDynamicSharedMemorySize, GEMM_SMEM);
    cudaFuncSetAttribute(moe_gemm<0>,
                         cudaFuncAttributeMaxDynamicSharedMemorySize, GEMM_SMEM);

    void* hbuf;
    cudaGetSymbolAddress(&hbuf, g_h);

    router_kernel<<<TOK / 128, 256>>>(x, rw);
    softmax_kernel<<<TOK / 8, 256>>>();
    zero_fanout<<<TOK / 256, 256>>>(out);
    topk_kernel<<<EXP, 1024, 131072>>>(out);

    // GEMM1: h = relu(x[idx] @ w1^T)^2   grid (N tiles, M tiles, E)
    moe_gemm<1><<<dim3(DIM / 128, CAP / 256, EXP), 256, GEMM_SMEM>>>(
        x, w1, (float*)hbuf);
    // GEMM2: out = h @ w2^T
    moe_gemm<0><<<dim3(HID / 128, CAP / 256, EXP), 256, GEMM_SMEM>>>(
        (const float*)hbuf, w2, out);
}

// round 17
// speedup vs baseline: 3.9165x; 1.3430x over previous
#include <cuda_runtime.h>
#include <cuda_fp16.h>
#include <cstdint>

// Problem constants
#define TOK   16384
#define EXP   64
#define HID   1024
#define DIM   1024
#define CAP   2048

typedef unsigned long long ull;

// ---------------- scratch (device globals) ----------------------------------
static __device__ float  g_logits [(size_t)TOK * EXP];
static __device__ float  g_logitsT[(size_t)EXP * TOK];
static __device__ float  g_weights[(size_t)TOK * EXP];
static __device__ int    g_idx    [EXP * CAP];
// fp16 hi/lo split operands (3xFP16 scheme)
static __device__ __half g_xh [(size_t)TOK * HID];
static __device__ __half g_xl [(size_t)TOK * HID];
static __device__ __half g_w1h[(size_t)EXP * DIM * HID];
static __device__ __half g_w1l[(size_t)EXP * DIM * HID];
static __device__ __half g_w2h[(size_t)EXP * HID * DIM];
static __device__ __half g_w2l[(size_t)EXP * HID * DIM];
static __device__ __half g_hh [(size_t)EXP * CAP * DIM];
static __device__ __half g_hl [(size_t)EXP * CAP * DIM];

// output layout
#define OUT_LI ((size_t)EXP * CAP * HID)
#define OUT_W  (OUT_LI + (size_t)EXP * CAP)
#define OUT_F  (OUT_W  + (size_t)EXP * CAP)

// ---------------- helpers ----------------------------------------------------
__device__ __forceinline__ uint32_t smem_u32(const void* p) {
    uint32_t a;
    asm("{ .reg .u64 t; cvta.to.shared.u64 t, %1; cvt.u32.u64 %0, t; }" : "=r"(a) : "l"(p));
    return a;
}
__device__ __forceinline__ void cp16(uint32_t dst, const void* src) {
    asm volatile("cp.async.cg.shared.global [%0], [%1], 16;" :: "r"(dst), "l"(src));
}
#define CP_COMMIT() asm volatile("cp.async.commit_group;" ::: "memory")
template <int N> __device__ __forceinline__ void cp_wait() {
    asm volatile("cp.async.wait_group %0;" :: "n"(N) : "memory");
}

// m16n8k16 fp16 tensor-core MMA, fp32 accumulate (baseline PTX, compute_103 ok)
__device__ __forceinline__ void mma16(float* c, const uint32_t* a, uint32_t b0, uint32_t b1) {
    asm volatile(
        "mma.sync.aligned.m16n8k16.row.col.f32.f16.f16.f32 "
        "{%0,%1,%2,%3}, {%4,%5,%6,%7}, {%8,%9}, {%0,%1,%2,%3};"
        : "+f"(c[0]), "+f"(c[1]), "+f"(c[2]), "+f"(c[3])
        : "r"(a[0]), "r"(a[1]), "r"(a[2]), "r"(a[3]), "r"(b0), "r"(b1));
}

// ---------------- 0. fp16 hi/lo split pre-pass -------------------------------
__global__ void split_kernel(const float4* __restrict__ src,
                             uint2* __restrict__ hi, uint2* __restrict__ lo, int n4) {
    for (int i = blockIdx.x * blockDim.x + threadIdx.x; i < n4; i += gridDim.x * blockDim.x) {
        float4 v = src[i];
        __half h0 = __float2half_rn(v.x), h1 = __float2half_rn(v.y);
        __half h2 = __float2half_rn(v.z), h3 = __float2half_rn(v.w);
        __half l0 = __float2half_rn(v.x - __half2float(h0));
        __half l1 = __float2half_rn(v.y - __half2float(h1));
        __half l2 = __float2half_rn(v.z - __half2float(h2));
        __half l3 = __float2half_rn(v.w - __half2float(h3));
        __half2 ph0 = __halves2half2(h0, h1), ph1 = __halves2half2(h2, h3);
        __half2 pl0 = __halves2half2(l0, l1), pl1 = __halves2half2(l2, l3);
        hi[i] = make_uint2(*(uint32_t*)&ph0, *(uint32_t*)&ph1);
        lo[i] = make_uint2(*(uint32_t*)&pl0, *(uint32_t*)&pl1);
    }
}

// ---------------- 1. router logits: BITWISE reference match (kc=512) --------
__global__ __launch_bounds__(256) void router_kernel(const float* __restrict__ x,
                                                     const float* __restrict__ rw) {
    __shared__ float xs[128][33];
    __shared__ float ws[64][33];
    int tid = threadIdx.x;
    int t_local = tid >> 1;
    int e_base  = (tid & 1) * 32;
    int t = blockIdx.x * 128 + t_local;

    float acc[32], p0[32];
    #pragma unroll
    for (int j = 0; j < 32; j++) { acc[j] = 0.f; p0[j] = 0.f; }

    for (int k0 = 0; k0 < HID; k0 += 32) {
        #pragma unroll
        for (int s = 0; s < 4; s++) {
            int f = tid + s * 256;
            int row = f >> 3, col = (f & 7) * 4;
            float4 v = *(const float4*)(x + (size_t)(blockIdx.x * 128 + row) * HID + k0 + col);
            xs[row][col + 0] = v.x; xs[row][col + 1] = v.y;
            xs[row][col + 2] = v.z; xs[row][col + 3] = v.w;
        }
        #pragma unroll
        for (int s = 0; s < 2; s++) {
            int f = tid + s * 256;
            int row = f >> 3, col = (f & 7) * 4;
            float4 v = *(const float4*)(rw + (size_t)row * HID + k0 + col);
            ws[row][col + 0] = v.x; ws[row][col + 1] = v.y;
            ws[row][col + 2] = v.z; ws[row][col + 3] = v.w;
        }
        __syncthreads();
        #pragma unroll 8
        for (int k = 0; k < 32; k++) {
            float xv = xs[t_local][k];
            #pragma unroll
            for (int j = 0; j < 32; j++)
                acc[j] = fmaf(xv, ws[e_base + j][k], acc[j]);
        }
        __syncthreads();
        if ((k0 + 32) == 512) {
            #pragma unroll
            for (int j = 0; j < 32; j++) { p0[j] = acc[j]; acc[j] = 0.f; }
        }
    }
    #pragma unroll
    for (int j = 0; j < 32; j++) {
        int e = e_base + j;
        float v = p0[j] + acc[j];
        g_logits [(size_t)t * EXP + e] = v;
        g_logitsT[(size_t)e * TOK + t] = v;
    }
}

// ---------------- 2. softmax -------------------------------------------------
__global__ void softmax_kernel() {
    int t    = blockIdx.x * 8 + (threadIdx.x >> 5);
    int lane = threadIdx.x & 31;
    float a = g_logits[(size_t)t * EXP + lane];
    float b = g_logits[(size_t)t * EXP + lane + 32];
    float m = fmaxf(a, b);
    #pragma unroll
    for (int o = 16; o > 0; o >>= 1) m = fmaxf(m, __shfl_xor_sync(0xffffffffu, m, o));
    float ea = expf(a - m), eb = expf(b - m);
    float s = ea + eb;
    #pragma unroll
    for (int o = 16; o > 0; o >>= 1) s += __shfl_xor_sync(0xffffffffu, s, o);
    g_weights[(size_t)t * EXP + lane]      = ea / s;
    g_weights[(size_t)t * EXP + lane + 32] = eb / s;
}

// ---------------- 3. fanout zero-init ---------------------------------------
__global__ void zero_fanout(float* out) {
    int i = blockIdx.x * blockDim.x + threadIdx.x;
    if (i < TOK) out[OUT_F + i] = 0.f;
}

// ---------------- 4. exact top-CAP bitonic sort ------------------------------
__global__ __launch_bounds__(1024) void topk_kernel(float* __restrict__ out) {
    int e = blockIdx.x;
    extern __shared__ ull keys[];
    const int N = TOK;
    for (int i = threadIdx.x; i < N; i += blockDim.x) {
        unsigned fu  = __float_as_uint(g_logitsT[(size_t)e * N + i]);
        unsigned asc = (fu & 0x80000000u) ? ~fu : (fu | 0x80000000u);
        keys[i] = ((ull)(~asc) << 32) | (unsigned)i;
    }
    __syncthreads();
    for (int k = 2; k <= N; k <<= 1) {
        for (int j = k >> 1; j > 0; j >>= 1) {
            for (int i = threadIdx.x; i < N; i += blockDim.x) {
                int ixj = i ^ j;
                if (ixj > i) {
                    ull a = keys[i], b = keys[ixj];
                    bool up = ((i & k) == 0);
                    if ((a > b) == up) { keys[i] = b; keys[ixj] = a; }
                }
            }
            __syncthreads();
        }
    }
    for (int i = threadIdx.x; i < CAP; i += blockDim.x) {
        unsigned tok = (unsigned)(keys[i] & 0xffffffffu);
        g_idx[e * CAP + i] = (int)tok;
        out[OUT_LI + (size_t)e * CAP + i] = (float)tok;
        out[OUT_W  + (size_t)e * CAP + i] = g_weights[(size_t)tok * EXP + e];
        atomicAdd(&out[OUT_F + tok], 1.0f);
    }
}

// ---------------- 5/6. 3xFP16 mma.sync expert GEMMs --------------------------
// CTA tile 256(M) x 128(N), 8 warps (4x2), warp tile 64x64.
// Operands pre-split to half hi/lo in GMEM; fragments = direct half2 LDS.
// k-chunk 16 (one k16 MMA), 3-stage cp.async pipeline.
// D += Ah*Bh + Ah*Bl + Al*Bh   (error ~2^-22)
#define BKC     16
#define NCHUNK  (HID / BKC)          // 64
#define ROWB    48                   // padded row: 24 halves (conflict-free)
#define SAH     0
#define SAL     (256 * ROWB)         // 12288
#define SBH     (2 * 256 * ROWB)     // 24576
#define SBL     (2 * 256 * ROWB + 128 * ROWB)
#define STAGE_B (2 * 256 * ROWB + 2 * 128 * ROWB)   // 36864
#define GEMM_SMEM (3 * STAGE_B)                      // 110592

template <int GATHER>
__device__ __forceinline__ void stage(
    uint32_t base, int c, int e, int mt, int nt,
    const __half* __restrict__ Ah, const __half* __restrict__ Al,
    const __half* __restrict__ Bh, const __half* __restrict__ Bl,
    const int* toks) {
    int tid = threadIdx.x;
    int k0 = c * BKC;
    // A: 256 rows x 16 halves (32B = 2 x cp16) for hi and lo
    #pragma unroll
    for (int s = 0; s < 2; s++) {
        int u = tid + s * 256;
        int row = u >> 1, seg = u & 1;
        size_t srow = GATHER ? (size_t)toks[row]
                             : ((size_t)e * CAP + (size_t)mt * 256 + row);
        size_t off = srow * (size_t)HID + k0 + seg * 8;
        uint32_t d = base + (uint32_t)(row * ROWB + seg * 16);
        cp16(d + SAH, Ah + off);
        cp16(d + SAL, Al + off);
    }
    // B: 128 rows x 16 halves
    {
        int row = tid >> 1, seg = tid & 1;
        size_t off = ((size_t)e * 1024 + (size_t)nt * 128 + row) * (size_t)HID + k0 + seg * 8;
        uint32_t d = base + (uint32_t)(row * ROWB + seg * 16);
        cp16(d + SBH, Bh + off);
        cp16(d + SBL, Bl + off);
    }
}

template <int GATHER>
__global__ __launch_bounds__(256, 1) void moe_gemm(
    const __half* __restrict__ Ah, const __half* __restrict__ Al,
    const __half* __restrict__ Bh, const __half* __restrict__ Bl,
    float* __restrict__ OutF, __half* __restrict__ OutHh, __half* __restrict__ OutHl) {
    extern __shared__ char smc[];
    uint32_t smem_base = smem_u32(smc);
    int e = blockIdx.z, mt = blockIdx.y, nt = blockIdx.x;
    int tid = threadIdx.x, wid = tid >> 5, lid = tid & 31;
    int wm = wid >> 1, wn = wid & 1;           // 4 x 2 warp grid
    int g = lid >> 2, t = lid & 3;

    __shared__ int toks[256];
    if (GATHER) {
        if (tid < 256) toks[tid] = g_idx[e * CAP + mt * 256 + tid];
        __syncthreads();
    }

    float cfr[4][8][4];
    #pragma unroll
    for (int i = 0; i < 4; i++)
        #pragma unroll
        for (int j = 0; j < 8; j++)
            #pragma unroll
            for (int r = 0; r < 4; r++) cfr[i][j][r] = 0.f;

    stage<GATHER>(smem_base,               0, e, mt, nt, Ah, Al, Bh, Bl, toks); CP_COMMIT();
    stage<GATHER>(smem_base + STAGE_B,     1, e, mt, nt, Ah, Al, Bh, Bl, toks); CP_COMMIT();
    stage<GATHER>(smem_base + 2 * STAGE_B, 2, e, mt, nt, Ah, Al, Bh, Bl, toks); CP_COMMIT();

    for (int c = 0; c < NCHUNK; c++) {
        if (c < NCHUNK - 2) cp_wait<2>();
        else if (c == NCHUNK - 2) cp_wait<1>();
        else cp_wait<0>();
        __syncthreads();

        const char* buf = smc + (c % 3) * STAGE_B;

        uint32_t ah[4][4], al[4][4];
        #pragma unroll
        for (int i = 0; i < 4; i++) {
            int r0 = wm * 64 + i * 16 + g;
            uint32_t o = (uint32_t)(r0 * ROWB + 4 * t);
            ah[i][0] = *(const uint32_t*)(buf + SAH + o);
            ah[i][1] = *(const uint32_t*)(buf + SAH + o + 8 * ROWB);
            ah[i][2] = *(const uint32_t*)(buf + SAH + o + 16);
            ah[i][3] = *(const uint32_t*)(buf + SAH + o + 8 * ROWB + 16);
            al[i][0] = *(const uint32_t*)(buf + SAL + o);
            al[i][1] = *(const uint32_t*)(buf + SAL + o + 8 * ROWB);
            al[i][2] = *(const uint32_t*)(buf + SAL + o + 16);
            al[i][3] = *(const uint32_t*)(buf + SAL + o + 8 * ROWB + 16);
        }
        #pragma unroll
        for (int j = 0; j < 8; j++) {
            int nr = wn * 64 + j * 8 + g;
            uint32_t o = (uint32_t)(nr * ROWB + 4 * t);
            uint32_t bh0 = *(const uint32_t*)(buf + SBH + o);
            uint32_t bh1 = *(const uint32_t*)(buf + SBH + o + 16);
            uint32_t bl0 = *(const uint32_t*)(buf + SBL + o);
            uint32_t bl1 = *(const uint32_t*)(buf + SBL + o + 16);
            #pragma unroll
            for (int i = 0; i < 4; i++) {
                mma16(cfr[i][j], ah[i], bh0, bh1);
                mma16(cfr[i][j], ah[i], bl0, bl1);
                mma16(cfr[i][j], al[i], bh0, bh1);
            }
        }
        __syncthreads();
        if (c + 3 < NCHUNK) {
            stage<GATHER>(smem_base + (c % 3) * STAGE_B, c + 3, e, mt, nt,
                          Ah, Al, Bh, Bl, toks);
            CP_COMMIT();
        }
    }

    // epilogue
    #pragma unroll
    for (int i = 0; i < 4; i++) {
        size_t row0 = (size_t)e * CAP + (size_t)mt * 256 + wm * 64 + i * 16 + g;
        #pragma unroll
        for (int j = 0; j < 8; j++) {
            size_t col = (size_t)nt * 128 + wn * 64 + j * 8 + 2 * t;
            #pragma unroll
            for (int h = 0; h < 2; h++) {
                size_t row = row0 + h * 8;
                float v0 = cfr[i][j][2 * h + 0];
                float v1 = cfr[i][j][2 * h + 1];
                if (GATHER) {                         // relu^2, emit half hi/lo
                    v0 = (v0 > 0.f) ? v0 * v0 : 0.f;
                    v1 = (v1 > 0.f) ? v1 * v1 : 0.f;
                    __half h0 = __float2half_rn(v0), h1 = __float2half_rn(v1);
                    __half2 ph = __halves2half2(h0, h1);
                    __half2 pl = __halves2half2(
                        __float2half_rn(v0 - __half2float(h0)),
                        __float2half_rn(v1 - __half2float(h1)));
                    *(__half2*)(OutHh + row * (size_t)DIM + col) = ph;
                    *(__half2*)(OutHl + row * (size_t)DIM + col) = pl;
                } else {
                    *(float2*)(OutF + row * (size_t)HID + col) = make_float2(v0, v1);
                }
            }
        }
    }
}

// ---------------- launch -----------------------------------------------------
extern "C" void kernel_launch(void* const* d_in, const int* in_sizes, int n_in,
                              void* d_out, int out_size) {
    const float* x  = (const float*)d_in[0];
    const float* rw = (const float*)d_in[1];
    const float* w1 = (const float*)d_in[2];
    const float* w2 = (const float*)d_in[3];
    float* out = (float*)d_out;

    cudaFuncSetAttribute(topk_kernel,
                         cudaFuncAttributeMaxDynamicSharedMemorySize, 131072);
    cudaFuncSetAttribute(moe_gemm<1>,
                         cudaFuncAttributeMaxDynamicSharedMemorySize, GEMM_SMEM);
    cudaFuncSetAttribute(moe_gemm<0>,
                         cudaFuncAttributeMaxDynamicSharedMemorySize, GEMM_SMEM);

    void *xh, *xl, *w1h, *w1l, *w2h, *w2l, *hh, *hl;
    cudaGetSymbolAddress(&xh,  g_xh);  cudaGetSymbolAddress(&xl,  g_xl);
    cudaGetSymbolAddress(&w1h, g_w1h); cudaGetSymbolAddress(&w1l, g_w1l);
    cudaGetSymbolAddress(&w2h, g_w2h); cudaGetSymbolAddress(&w2l, g_w2l);
    cudaGetSymbolAddress(&hh,  g_hh);  cudaGetSymbolAddress(&hl,  g_hl);

    split_kernel<<<2048, 256>>>((const float4*)x,  (uint2*)xh,  (uint2*)xl,  TOK * HID / 4);
    split_kernel<<<4096, 256>>>((const float4*)w1, (uint2*)w1h, (uint2*)w1l, EXP * DIM * HID / 4);
    split_kernel<<<4096, 256>>>((const float4*)w2, (uint2*)w2h, (uint2*)w2l, EXP * HID * DIM / 4);

    router_kernel<<<TOK / 128, 256>>>(x, rw);
    softmax_kernel<<<TOK / 8, 256>>>();
    zero_fanout<<<TOK / 256, 256>>>(out);
    topk_kernel<<<EXP, 1024, 131072>>>(out);

    // GEMM1: h = relu(x[idx] @ w1^T)^2 -> half hi/lo    grid (N, M, E)
    moe_gemm<1><<<dim3(DIM / 128, CAP / 256, EXP), 256, GEMM_SMEM>>>(
        (const __half*)xh, (const __half*)xl, (const __half*)w1h, (const __half*)w1l,
        nullptr, (__half*)hh, (__half*)hl);
    // GEMM2: out = h @ w2^T
    moe_gemm<0><<<dim3(HID / 128, CAP / 256, EXP), 256, GEMM_SMEM>>>(
        (const __half*)hh, (const __half*)hl, (const __half*)w2h, (const __half*)w2l,
        out, nullptr, nullptr);
}